// round 11
// baseline (speedup 1.0000x reference)
#include <cuda_runtime.h>
#include <cuda_bf16.h>

// Problem constants
#define Bn 16
#define Cn 128
#define Hn 64
#define Wn 64
#define HWn 4096
#define TDn 256
#define CDn 256
#define En 8
#define FEAT (Cn + TDn + CDn)   // 640
#define NPB 32                  // pixel-blocks per batch in pw GEMM (4096/128)

// ---------------- scratch (device globals; no allocation allowed) -------------
__device__ float g_dw[Bn * Cn * HWn];        // proj depthwise output
__device__ float g_xproj[Bn * Cn * HWn];     // proj output
__device__ float g_edw[Bn * 2 * Cn * HWn];   // expert depthwise outputs (2 slots)
__device__ float g_part[Bn * Cn * NPB];      // pooled partial sums
__device__ int   g_idx[Bn * 2];
__device__ float g_wts[Bn * 2];

// ---------------- depthwise 3x3 (SAME, zero pad) ------------------------------
__device__ __forceinline__ void dw_stage(const float* __restrict__ plane,
                                         float* __restrict__ s /* 66*66 */) {
    for (int idx = threadIdx.x; idx < 66 * 66; idx += blockDim.x) {
        int i = idx / 66, j = idx - i * 66;
        int h = i - 1, w = j - 1;
        s[idx] = (h >= 0 && h < Hn && w >= 0 && w < Wn) ? plane[h * Wn + w] : 0.f;
    }
    __syncthreads();
}

__global__ __launch_bounds__(256) void dw_proj_kernel(const float* __restrict__ x,
                                                      const float* __restrict__ pdw,
                                                      const float* __restrict__ pdwb) {
    __shared__ float s[66 * 66];
    int c = blockIdx.x, b = blockIdx.y;
    const float* w9 = pdw + c * 9;
    float wr[9];
#pragma unroll
    for (int i = 0; i < 9; i++) wr[i] = w9[i];
    float bias = pdwb[c];
    dw_stage(x + (b * Cn + c) * HWn, s);
    float* op = g_dw + (b * Cn + c) * HWn;
#pragma unroll 4
    for (int p = threadIdx.x; p < HWn; p += 256) {
        int h = p >> 6, w = p & 63;
        const float* sp = s + h * 66 + w;
        float acc = bias;
        acc += sp[0]   * wr[0] + sp[1]   * wr[1] + sp[2]   * wr[2];
        acc += sp[66]  * wr[3] + sp[67]  * wr[4] + sp[68]  * wr[5];
        acc += sp[132] * wr[6] + sp[133] * wr[7] + sp[134] * wr[8];
        op[p] = acc;
    }
}

// One block per (c,b): stage the x_proj plane ONCE, produce BOTH routed slots.
__global__ __launch_bounds__(256) void dw_expert_both(const float* __restrict__ edw,
                                                      const float* __restrict__ edwb) {
    __shared__ float s[66 * 66];
    int c = blockIdx.x, b = blockIdx.y;
    int e0 = g_idx[b * 2 + 0], e1 = g_idx[b * 2 + 1];
    float wr0[9], wr1[9];
    const float* w0p = edw + (e0 * Cn + c) * 9;
    const float* w1p = edw + (e1 * Cn + c) * 9;
#pragma unroll
    for (int i = 0; i < 9; i++) { wr0[i] = w0p[i]; wr1[i] = w1p[i]; }
    float b0 = edwb[e0 * Cn + c];
    float b1 = edwb[e1 * Cn + c];

    dw_stage(g_xproj + (b * Cn + c) * HWn, s);

    float* op0 = g_edw + ((b * 2 + 0) * Cn + c) * HWn;
    float* op1 = g_edw + ((b * 2 + 1) * Cn + c) * HWn;
#pragma unroll 4
    for (int p = threadIdx.x; p < HWn; p += 256) {
        int h = p >> 6, w = p & 63;
        const float* sp = s + h * 66 + w;
        float v0 = sp[0], v1 = sp[1], v2 = sp[2];
        float v3 = sp[66], v4 = sp[67], v5 = sp[68];
        float v6 = sp[132], v7 = sp[133], v8 = sp[134];
        float a0 = b0 + v0 * wr0[0] + v1 * wr0[1] + v2 * wr0[2]
                      + v3 * wr0[3] + v4 * wr0[4] + v5 * wr0[5]
                      + v6 * wr0[6] + v7 * wr0[7] + v8 * wr0[8];
        float a1 = b1 + v0 * wr1[0] + v1 * wr1[1] + v2 * wr1[2]
                      + v3 * wr1[3] + v4 * wr1[4] + v5 * wr1[5]
                      + v6 * wr1[6] + v7 * wr1[7] + v8 * wr1[8];
        op0[p] = a0;
        op1[p] = a1;
    }
}

// ---------------- pointwise 1x1 GEMM: BM=BN=128, BK=16, 256 thr, 8x8/thr ------
// Double-buffered smem pipeline; one __syncthreads per k-stage.
// As uses an XOR-8 column swizzle keyed on (row>>2)&3 so the K-major A stores
// are bank-conflict-free while float4 reads stay aligned and contiguous.
#define BM 128
#define BN 128
#define BK 16

__device__ __forceinline__ void gemm_pass(const float* __restrict__ Wm,
                                          const float* __restrict__ Bmat,
                                          int p0, int tid, int tx, int ty,
                                          float (&acc)[8][8],
                                          float (*As)[BM], float (*Bs)[BN]) {
    const int a_row = tid >> 2;            // 0..63 (t adds 64)
    const int a_kq  = (tid & 3) * 4;       // k sub-offset 0,4,8,12
    const int a_cs  = (tid & 3) * 8;       // column swizzle = ((row>>2)&3)<<3
    const int b_kr  = tid >> 5;            // 0..7 (t adds 8)
    const int b_cq  = (tid & 31) * 4;      // pixel sub-offset

    float4 ra[2], rb[2];

    // prologue: global loads for stage 0
#pragma unroll
    for (int t = 0; t < 2; t++) {
        ra[t] = *(const float4*)(Wm + (a_row + t * 64) * Cn + a_kq);
        rb[t] = *(const float4*)(Bmat + (b_kr + t * 8) * HWn + p0 + b_cq);
    }
#pragma unroll
    for (int t = 0; t < 2; t++) {
        int r = (a_row + t * 64) ^ a_cs;
        As[a_kq + 0][r] = ra[t].x;
        As[a_kq + 1][r] = ra[t].y;
        As[a_kq + 2][r] = ra[t].z;
        As[a_kq + 3][r] = ra[t].w;
        *(float4*)&Bs[b_kr + t * 8][b_cq] = rb[t];
    }
    __syncthreads();

#pragma unroll
    for (int ks = 0; ks < Cn / BK; ks++) {
        int cur = ks & 1;
        if (ks < Cn / BK - 1) {
            int k0 = (ks + 1) * BK;
#pragma unroll
            for (int t = 0; t < 2; t++) {
                ra[t] = *(const float4*)(Wm + (a_row + t * 64) * Cn + k0 + a_kq);
                rb[t] = *(const float4*)(Bmat + (k0 + b_kr + t * 8) * HWn + p0 + b_cq);
            }
        }
        float (*Ac)[BM] = As + cur * BK;
        float (*Bc)[BN] = Bs + cur * BK;
#pragma unroll
        for (int kk = 0; kk < BK; kk++) {
            int c = ((kk >> 2) & 3) << 3;      // matches store-side swizzle
            int ab = (ty * 8) ^ c;
            float4 a0 = *(float4*)&Ac[kk][ab];
            float4 a1 = *(float4*)&Ac[kk][ab + 4];
            float4 b0 = *(float4*)&Bc[kk][tx * 4];
            float4 b1 = *(float4*)&Bc[kk][64 + tx * 4];
            float a[8] = {a0.x, a0.y, a0.z, a0.w, a1.x, a1.y, a1.z, a1.w};
            float bb[8] = {b0.x, b0.y, b0.z, b0.w, b1.x, b1.y, b1.z, b1.w};
#pragma unroll
            for (int i = 0; i < 8; i++)
#pragma unroll
                for (int j = 0; j < 8; j++)
                    acc[i][j] += a[i] * bb[j];
        }
        if (ks < Cn / BK - 1) {
            int nb = 1 - cur;
#pragma unroll
            for (int t = 0; t < 2; t++) {
                int r = (a_row + t * 64) ^ a_cs;
                As[nb * BK + a_kq + 0][r] = ra[t].x;
                As[nb * BK + a_kq + 1][r] = ra[t].y;
                As[nb * BK + a_kq + 2][r] = ra[t].z;
                As[nb * BK + a_kq + 3][r] = ra[t].w;
                *(float4*)&Bs[nb * BK + b_kr + t * 8][b_cq] = rb[t];
            }
        }
        __syncthreads();
    }
}

// proj GEMM + fused pooled partial sums (deterministic shfl reduction)
__global__ __launch_bounds__(256) void pw_proj_gemm(const float* __restrict__ Wm,
                                                    const float* __restrict__ bias) {
    __shared__ float As[2 * BK][BM];
    __shared__ float Bs[2 * BK][BN];
    int b = blockIdx.z;
    int blk = blockIdx.x;
    int p0 = blk * BN;
    int tid = threadIdx.x;
    int tx = tid & 15, ty = tid >> 4;
    float acc[8][8] = {};
    gemm_pass(Wm, g_dw + b * Cn * HWn, p0, tid, tx, ty, acc, As, Bs);
    float* Cm = g_xproj + b * Cn * HWn;
#pragma unroll
    for (int i = 0; i < 8; i++) {
        int co = ty * 8 + i;
        float bv = bias[co];
        float4 o0 = make_float4(acc[i][0] + bv, acc[i][1] + bv,
                                acc[i][2] + bv, acc[i][3] + bv);
        float4 o1 = make_float4(acc[i][4] + bv, acc[i][5] + bv,
                                acc[i][6] + bv, acc[i][7] + bv);
        *(float4*)(Cm + co * HWn + p0 + tx * 4) = o0;
        *(float4*)(Cm + co * HWn + p0 + 64 + tx * 4) = o1;
        // pooled partial: sum of this thread's 8 pixels (pre-bias)
        float ps = ((acc[i][0] + acc[i][1]) + (acc[i][2] + acc[i][3]))
                 + ((acc[i][4] + acc[i][5]) + (acc[i][6] + acc[i][7]));
        // reduce across the 16 tx-lanes sharing this ty (contiguous half-warp)
#pragma unroll
        for (int off = 8; off > 0; off >>= 1)
            ps += __shfl_down_sync(0xffffffffu, ps, off, 16);
        if (tx == 0)
            g_part[(b * Cn + co) * NPB + blk] = ps;
    }
}

__device__ __forceinline__ float silu_f(float v) {
    return v / (1.f + __expf(-v));
}

__global__ __launch_bounds__(256) void pw_expert_gemm(const float* __restrict__ Wall,
                                                      const float* __restrict__ ball,
                                                      float* __restrict__ out) {
    __shared__ float As[2 * BK][BM];
    __shared__ float Bs[2 * BK][BN];
    int b = blockIdx.z;
    int p0 = blockIdx.x * BN;
    int tid = threadIdx.x;
    int tx = tid & 15, ty = tid >> 4;
    int e0 = g_idx[b * 2 + 0], e1 = g_idx[b * 2 + 1];
    float w0 = g_wts[b * 2 + 0], w1 = g_wts[b * 2 + 1];

    float acc[8][8] = {};
    float o[8][8];

    // slot 0
    gemm_pass(Wall + e0 * Cn * Cn, g_edw + (b * 2 + 0) * Cn * HWn,
              p0, tid, tx, ty, acc, As, Bs);
#pragma unroll
    for (int i = 0; i < 8; i++) {
        float bv = ball[e0 * Cn + ty * 8 + i];
#pragma unroll
        for (int j = 0; j < 8; j++) {
            o[i][j] = w0 * silu_f(acc[i][j] + bv);
            acc[i][j] = 0.f;
        }
    }
    __syncthreads();
    // slot 1
    gemm_pass(Wall + e1 * Cn * Cn, g_edw + (b * 2 + 1) * Cn * HWn,
              p0, tid, tx, ty, acc, As, Bs);

    float* Cm = out + b * Cn * HWn;
#pragma unroll
    for (int i = 0; i < 8; i++) {
        int co = ty * 8 + i;
        float bv = ball[e1 * Cn + co];
        float4 o0, o1;
        o0.x = o[i][0] + w1 * silu_f(acc[i][0] + bv);
        o0.y = o[i][1] + w1 * silu_f(acc[i][1] + bv);
        o0.z = o[i][2] + w1 * silu_f(acc[i][2] + bv);
        o0.w = o[i][3] + w1 * silu_f(acc[i][3] + bv);
        o1.x = o[i][4] + w1 * silu_f(acc[i][4] + bv);
        o1.y = o[i][5] + w1 * silu_f(acc[i][5] + bv);
        o1.z = o[i][6] + w1 * silu_f(acc[i][6] + bv);
        o1.w = o[i][7] + w1 * silu_f(acc[i][7] + bv);
        *(float4*)(Cm + co * HWn + p0 + tx * 4) = o0;
        *(float4*)(Cm + co * HWn + p0 + 64 + tx * 4) = o1;
    }
}

// ---------------- router: fold partials + MLP + top2 + softmax ----------------
__global__ __launch_bounds__(128) void router_kernel(const float* __restrict__ t_emb,
                                                     const float* __restrict__ c_emb,
                                                     const float* __restrict__ pwb,
                                                     const float* __restrict__ w1,
                                                     const float* __restrict__ b1,
                                                     const float* __restrict__ w2,
                                                     const float* __restrict__ b2,
                                                     float* __restrict__ logits_out) {
    int b = blockIdx.x;
    int tid = threadIdx.x;
    __shared__ float feat[FEAT];
    __shared__ float h[Cn];
    __shared__ float lg[En];

    // fold pooled partials for channel `tid` (fixed order -> deterministic)
    {
        const float* pp = g_part + (b * Cn + tid) * NPB;
        float sum = 0.f;
#pragma unroll
        for (int k = 0; k < NPB; k++) sum += pp[k];
        feat[tid] = sum * (1.f / (float)HWn) + pwb[tid];
    }
    for (int k = tid; k < TDn; k += 128) feat[Cn + k] = t_emb[b * TDn + k];
    for (int k = tid; k < CDn; k += 128) feat[Cn + TDn + k] = c_emb[b * CDn + k];
    __syncthreads();

    float s = b1[tid];
    for (int k = 0; k < FEAT; k++) s += feat[k] * w1[k * Cn + tid];
    h[tid] = silu_f(s);
    __syncthreads();

    if (tid < En) {
        float acc = b2[tid];
        for (int j = 0; j < Cn; j++) acc += h[j] * w2[j * En + tid];
        lg[tid] = acc;
        logits_out[b * En + tid] = acc;
    }
    __syncthreads();

    if (tid == 0) {
        int i0 = 0;
        float v0 = lg[0];
#pragma unroll
        for (int e = 1; e < En; e++)
            if (lg[e] > v0) { v0 = lg[e]; i0 = e; }
        int i1 = -1;
        float v1 = -3.4e38f;
#pragma unroll
        for (int e = 0; e < En; e++)
            if (e != i0 && lg[e] > v1) { v1 = lg[e]; i1 = e; }
        // softmax over (v0, v1), v0 >= v1
        float e1x = __expf(v1 - v0);
        float inv = 1.f / (1.f + e1x);
        g_idx[b * 2 + 0] = i0;
        g_idx[b * 2 + 1] = i1;
        g_wts[b * 2 + 0] = inv;
        g_wts[b * 2 + 1] = e1x * inv;
    }
}

// ---------------- launcher ----------------------------------------------------
extern "C" void kernel_launch(void* const* d_in, const int* in_sizes, int n_in,
                              void* d_out, int out_size) {
    const float* x        = (const float*)d_in[0];
    const float* t_emb    = (const float*)d_in[1];
    const float* c_emb    = (const float*)d_in[2];
    const float* proj_dw  = (const float*)d_in[3];
    const float* proj_dwb = (const float*)d_in[4];
    const float* proj_pw  = (const float*)d_in[5];
    const float* proj_pwb = (const float*)d_in[6];
    const float* rw1      = (const float*)d_in[7];
    const float* rb1      = (const float*)d_in[8];
    const float* rw2      = (const float*)d_in[9];
    const float* rb2      = (const float*)d_in[10];
    const float* exp_dw   = (const float*)d_in[11];
    const float* exp_dwb  = (const float*)d_in[12];
    const float* exp_pw   = (const float*)d_in[13];
    const float* exp_pwb  = (const float*)d_in[14];
    float* out = (float*)d_out;

    // 1) proj depthwise
    dw_proj_kernel<<<dim3(Cn, Bn), 256>>>(x, proj_dw, proj_dwb);
    // 2) proj pointwise GEMM + fused pooled partials
    pw_proj_gemm<<<dim3(NPB, 1, Bn), 256>>>(proj_pw, proj_pwb);
    // 3) router (folds partials, writes logits into tail of d_out)
    router_kernel<<<Bn, 128>>>(t_emb, c_emb, proj_pwb, rw1, rb1, rw2, rb2,
                               out + Bn * Cn * HWn);
    // 4) expert depthwise: both routed slots from one staged tile
    dw_expert_both<<<dim3(Cn, Bn), 256>>>(exp_dw, exp_dwb);
    // 5) expert pointwise + silu + weighted combine -> out
    pw_expert_gemm<<<dim3(NPB, 1, Bn), 256>>>(exp_pw, exp_pwb, out);
}

// round 15
// speedup vs baseline: 2.3090x; 2.3090x over previous
#include <cuda_runtime.h>
#include <cuda_bf16.h>

// Problem constants
#define Bn 16
#define Cn 128
#define Hn 64
#define Wn 64
#define HWn 4096
#define TDn 256
#define CDn 256
#define En 8
#define FEAT (Cn + TDn + CDn)   // 640
#define NPB 32                  // pixel-blocks per batch (4096/128)
#define NPB2 (NPB * 4)          // pooled partials per channel (per warp_n)

// tf32 GEMM tiling
#define BKt 16
#define APAD 20                 // A_s row stride in words (conflict-free frag reads)
#define BPAD 136                // B_s row stride in words (conflict-free frag reads)

// ---------------- scratch (device globals; no allocation allowed) -------------
__device__ float g_dw[Bn * Cn * HWn];        // proj depthwise output
__device__ float g_xproj[Bn * Cn * HWn];     // proj output
__device__ float g_edw[Bn * 2 * Cn * HWn];   // expert depthwise outputs (2 slots)
__device__ float g_part[Bn * Cn * NPB2];     // pooled partial sums
__device__ int   g_idx[Bn * 2];
__device__ float g_wts[Bn * 2];

// ---------------- depthwise 3x3 (SAME, zero pad) ------------------------------
__device__ __forceinline__ void dw_stage(const float* __restrict__ plane,
                                         float* __restrict__ s /* 66*66 */) {
    for (int idx = threadIdx.x; idx < 66 * 66; idx += blockDim.x) {
        int i = idx / 66, j = idx - i * 66;
        int h = i - 1, w = j - 1;
        s[idx] = (h >= 0 && h < Hn && w >= 0 && w < Wn) ? plane[h * Wn + w] : 0.f;
    }
    __syncthreads();
}

__global__ __launch_bounds__(256) void dw_proj_kernel(const float* __restrict__ x,
                                                      const float* __restrict__ pdw,
                                                      const float* __restrict__ pdwb) {
    __shared__ float s[66 * 66];
    int c = blockIdx.x, b = blockIdx.y;
    const float* w9 = pdw + c * 9;
    float wr[9];
#pragma unroll
    for (int i = 0; i < 9; i++) wr[i] = w9[i];
    float bias = pdwb[c];
    dw_stage(x + (b * Cn + c) * HWn, s);
    float* op = g_dw + (b * Cn + c) * HWn;
#pragma unroll 4
    for (int p = threadIdx.x; p < HWn; p += 256) {
        int h = p >> 6, w = p & 63;
        const float* sp = s + h * 66 + w;
        float acc = bias;
        acc += sp[0]   * wr[0] + sp[1]   * wr[1] + sp[2]   * wr[2];
        acc += sp[66]  * wr[3] + sp[67]  * wr[4] + sp[68]  * wr[5];
        acc += sp[132] * wr[6] + sp[133] * wr[7] + sp[134] * wr[8];
        op[p] = acc;
    }
}

__global__ __launch_bounds__(256) void dw_expert_both(const float* __restrict__ edw,
                                                      const float* __restrict__ edwb) {
    __shared__ float s[66 * 66];
    int c = blockIdx.x, b = blockIdx.y;
    int e0 = g_idx[b * 2 + 0], e1 = g_idx[b * 2 + 1];
    float wr0[9], wr1[9];
    const float* w0p = edw + (e0 * Cn + c) * 9;
    const float* w1p = edw + (e1 * Cn + c) * 9;
#pragma unroll
    for (int i = 0; i < 9; i++) { wr0[i] = w0p[i]; wr1[i] = w1p[i]; }
    float b0 = edwb[e0 * Cn + c];
    float b1 = edwb[e1 * Cn + c];

    dw_stage(g_xproj + (b * Cn + c) * HWn, s);

    float* op0 = g_edw + ((b * 2 + 0) * Cn + c) * HWn;
    float* op1 = g_edw + ((b * 2 + 1) * Cn + c) * HWn;
#pragma unroll 4
    for (int p = threadIdx.x; p < HWn; p += 256) {
        int h = p >> 6, w = p & 63;
        const float* sp = s + h * 66 + w;
        float v0 = sp[0], v1 = sp[1], v2 = sp[2];
        float v3 = sp[66], v4 = sp[67], v5 = sp[68];
        float v6 = sp[132], v7 = sp[133], v8 = sp[134];
        float a0 = b0 + v0 * wr0[0] + v1 * wr0[1] + v2 * wr0[2]
                      + v3 * wr0[3] + v4 * wr0[4] + v5 * wr0[5]
                      + v6 * wr0[6] + v7 * wr0[7] + v8 * wr0[8];
        float a1 = b1 + v0 * wr1[0] + v1 * wr1[1] + v2 * wr1[2]
                      + v3 * wr1[3] + v4 * wr1[4] + v5 * wr1[5]
                      + v6 * wr1[6] + v7 * wr1[7] + v8 * wr1[8];
        op0[p] = a0;
        op1[p] = a1;
    }
}

// ---------------- tf32 tensor-core 1x1-conv GEMM ------------------------------
// CTA: 128 (co) x 128 (pixels), K=128; 8 warps in 2x4 (M x N); warp tile 64x32;
// mma.sync m16n8k8 tf32, fp32 accumulate. Double-buffered smem, BK=16.

__device__ __forceinline__ unsigned f2tf32(float f) {
    unsigned u;
    asm("cvt.rna.tf32.f32 %0, %1;" : "=r"(u) : "f"(f));
    return u;
}

__device__ __forceinline__ void mma_tf32(float* c, const unsigned* a, const unsigned* b) {
    asm volatile(
        "mma.sync.aligned.m16n8k8.row.col.f32.tf32.tf32.f32 "
        "{%0,%1,%2,%3}, {%4,%5,%6,%7}, {%8,%9}, {%0,%1,%2,%3};"
        : "+f"(c[0]), "+f"(c[1]), "+f"(c[2]), "+f"(c[3])
        : "r"(a[0]), "r"(a[1]), "r"(a[2]), "r"(a[3]), "r"(b[0]), "r"(b[1]));
}

// Wm: [128 co][128 ci] row-major; Bmat: [128 ci][HWn pixels]; tile at pixel p0.
__device__ __forceinline__ void gemm_pass_tf32(const float* __restrict__ Wm,
                                               const float* __restrict__ Bmat,
                                               int p0, int tid,
                                               float (&c)[4][4][4],
                                               unsigned (*As)[APAD],
                                               unsigned (*Bs)[BPAD]) {
    const int lane = tid & 31, warp = tid >> 5;
    const int wm = warp >> 2, wn = warp & 3;
    const int g = lane >> 2, tig = lane & 3;
    const int a_co = tid >> 2, a_kq = (tid & 3) * 4;   // +64 co for t=1
    const int b_kr = tid >> 5, b_cq = (tid & 31) * 4;  // +8 kr for t=1

    float4 va[2], vb[2];

    // prologue: stage 0 loads
#pragma unroll
    for (int t = 0; t < 2; t++) {
        va[t] = *(const float4*)(Wm + (a_co + t * 64) * Cn + a_kq);
        vb[t] = *(const float4*)(Bmat + (b_kr + t * 8) * HWn + p0 + b_cq);
    }
#pragma unroll
    for (int t = 0; t < 2; t++) {
        *(uint4*)&As[a_co + t * 64][a_kq] =
            make_uint4(f2tf32(va[t].x), f2tf32(va[t].y), f2tf32(va[t].z), f2tf32(va[t].w));
        *(uint4*)&Bs[b_kr + t * 8][b_cq] =
            make_uint4(f2tf32(vb[t].x), f2tf32(vb[t].y), f2tf32(vb[t].z), f2tf32(vb[t].w));
    }
    __syncthreads();

#pragma unroll
    for (int ks = 0; ks < Cn / BKt; ks++) {
        int cur = ks & 1;
        if (ks < Cn / BKt - 1) {
            int k0 = (ks + 1) * BKt;
#pragma unroll
            for (int t = 0; t < 2; t++) {
                va[t] = *(const float4*)(Wm + (a_co + t * 64) * Cn + k0 + a_kq);
                vb[t] = *(const float4*)(Bmat + (k0 + b_kr + t * 8) * HWn + p0 + b_cq);
            }
        }
        unsigned (*Ac)[APAD] = As + cur * 128;
        unsigned (*Bc)[BPAD] = Bs + cur * BKt;
#pragma unroll
        for (int k8 = 0; k8 < BKt; k8 += 8) {
            unsigned af[4][4], bf[4][2];
#pragma unroll
            for (int mt = 0; mt < 4; mt++) {
                int rm = wm * 64 + mt * 16;
                af[mt][0] = Ac[rm + g][k8 + tig];
                af[mt][1] = Ac[rm + g + 8][k8 + tig];
                af[mt][2] = Ac[rm + g][k8 + tig + 4];
                af[mt][3] = Ac[rm + g + 8][k8 + tig + 4];
            }
#pragma unroll
            for (int nt = 0; nt < 4; nt++) {
                int cn = wn * 32 + nt * 8;
                bf[nt][0] = Bc[k8 + tig][cn + g];
                bf[nt][1] = Bc[k8 + tig + 4][cn + g];
            }
#pragma unroll
            for (int mt = 0; mt < 4; mt++)
#pragma unroll
                for (int nt = 0; nt < 4; nt++)
                    mma_tf32(c[mt][nt], af[mt], bf[nt]);
        }
        if (ks < Cn / BKt - 1) {
            int nb = 1 - cur;
#pragma unroll
            for (int t = 0; t < 2; t++) {
                *(uint4*)&As[nb * 128 + a_co + t * 64][a_kq] =
                    make_uint4(f2tf32(va[t].x), f2tf32(va[t].y), f2tf32(va[t].z), f2tf32(va[t].w));
                *(uint4*)&Bs[nb * BKt + b_kr + t * 8][b_cq] =
                    make_uint4(f2tf32(vb[t].x), f2tf32(vb[t].y), f2tf32(vb[t].z), f2tf32(vb[t].w));
            }
        }
        __syncthreads();
    }
}

// proj GEMM + fused pooled partials (deterministic quad-shfl reduction)
__global__ __launch_bounds__(256) void pw_proj_gemm(const float* __restrict__ Wm,
                                                    const float* __restrict__ bias) {
    __shared__ unsigned As[2 * 128][APAD];
    __shared__ unsigned Bs[2 * BKt][BPAD];
    int b = blockIdx.z;
    int blk = blockIdx.x;
    int p0 = blk * 128;
    int tid = threadIdx.x;
    const int lane = tid & 31, warp = tid >> 5;
    const int wm = warp >> 2, wn = warp & 3;
    const int g = lane >> 2, tig = lane & 3;

    float c[4][4][4] = {};
    gemm_pass_tf32(Wm, g_dw + b * Cn * HWn, p0, tid, c, As, Bs);

    float* Cm = g_xproj + b * Cn * HWn;
#pragma unroll
    for (int mt = 0; mt < 4; mt++) {
        int r0 = wm * 64 + mt * 16 + g;
        float bv0 = bias[r0], bv1 = bias[r0 + 8];
        float rs0 = 0.f, rs1 = 0.f;
#pragma unroll
        for (int nt = 0; nt < 4; nt++) {
            int col = p0 + wn * 32 + nt * 8 + tig * 2;
            float v00 = c[mt][nt][0], v01 = c[mt][nt][1];
            float v10 = c[mt][nt][2], v11 = c[mt][nt][3];
            rs0 += v00 + v01;
            rs1 += v10 + v11;
            float2 u0 = make_float2(v00 + bv0, v01 + bv0);
            float2 u1 = make_float2(v10 + bv1, v11 + bv1);
            *(float2*)(Cm + r0 * HWn + col) = u0;
            *(float2*)(Cm + (r0 + 8) * HWn + col) = u1;
        }
        // reduce across the 4 tig lanes of this quad (fixed order, deterministic)
        rs0 += __shfl_xor_sync(0xffffffffu, rs0, 1);
        rs0 += __shfl_xor_sync(0xffffffffu, rs0, 2);
        rs1 += __shfl_xor_sync(0xffffffffu, rs1, 1);
        rs1 += __shfl_xor_sync(0xffffffffu, rs1, 2);
        if (tig == 0) {
            g_part[(b * Cn + r0) * NPB2 + blk * 4 + wn] = rs0;
            g_part[(b * Cn + r0 + 8) * NPB2 + blk * 4 + wn] = rs1;
        }
    }
}

__device__ __forceinline__ float silu_f(float v) {
    return v / (1.f + __expf(-v));
}

__global__ __launch_bounds__(256) void pw_expert_gemm(const float* __restrict__ Wall,
                                                      const float* __restrict__ ball,
                                                      float* __restrict__ out) {
    __shared__ unsigned As[2 * 128][APAD];
    __shared__ unsigned Bs[2 * BKt][BPAD];
    int b = blockIdx.z;
    int p0 = blockIdx.x * 128;
    int tid = threadIdx.x;
    const int lane = tid & 31, warp = tid >> 5;
    const int wm = warp >> 2, wn = warp & 3;
    const int g = lane >> 2, tig = lane & 3;
    int e0 = g_idx[b * 2 + 0], e1 = g_idx[b * 2 + 1];
    float w0 = g_wts[b * 2 + 0], w1 = g_wts[b * 2 + 1];

    float c[4][4][4] = {};
    float o[4][4][4];

    // slot 0
    gemm_pass_tf32(Wall + e0 * Cn * Cn, g_edw + (b * 2 + 0) * Cn * HWn,
                   p0, tid, c, As, Bs);
#pragma unroll
    for (int mt = 0; mt < 4; mt++) {
        int r0 = wm * 64 + mt * 16 + g;
        float bva = ball[e0 * Cn + r0];
        float bvb = ball[e0 * Cn + r0 + 8];
#pragma unroll
        for (int nt = 0; nt < 4; nt++) {
            o[mt][nt][0] = w0 * silu_f(c[mt][nt][0] + bva);
            o[mt][nt][1] = w0 * silu_f(c[mt][nt][1] + bva);
            o[mt][nt][2] = w0 * silu_f(c[mt][nt][2] + bvb);
            o[mt][nt][3] = w0 * silu_f(c[mt][nt][3] + bvb);
            c[mt][nt][0] = 0.f; c[mt][nt][1] = 0.f;
            c[mt][nt][2] = 0.f; c[mt][nt][3] = 0.f;
        }
    }
    // slot 1
    gemm_pass_tf32(Wall + e1 * Cn * Cn, g_edw + (b * 2 + 1) * Cn * HWn,
                   p0, tid, c, As, Bs);

    float* Cm = out + b * Cn * HWn;
#pragma unroll
    for (int mt = 0; mt < 4; mt++) {
        int r0 = wm * 64 + mt * 16 + g;
        float bva = ball[e1 * Cn + r0];
        float bvb = ball[e1 * Cn + r0 + 8];
#pragma unroll
        for (int nt = 0; nt < 4; nt++) {
            int col = p0 + wn * 32 + nt * 8 + tig * 2;
            float2 u0 = make_float2(o[mt][nt][0] + w1 * silu_f(c[mt][nt][0] + bva),
                                    o[mt][nt][1] + w1 * silu_f(c[mt][nt][1] + bva));
            float2 u1 = make_float2(o[mt][nt][2] + w1 * silu_f(c[mt][nt][2] + bvb),
                                    o[mt][nt][3] + w1 * silu_f(c[mt][nt][3] + bvb));
            *(float2*)(Cm + r0 * HWn + col) = u0;
            *(float2*)(Cm + (r0 + 8) * HWn + col) = u1;
        }
    }
}

// ---------------- router: fold partials + MLP + top2 + softmax ----------------
__global__ __launch_bounds__(128) void router_kernel(const float* __restrict__ t_emb,
                                                     const float* __restrict__ c_emb,
                                                     const float* __restrict__ pwb,
                                                     const float* __restrict__ w1,
                                                     const float* __restrict__ b1,
                                                     const float* __restrict__ w2,
                                                     const float* __restrict__ b2,
                                                     float* __restrict__ logits_out) {
    int b = blockIdx.x;
    int tid = threadIdx.x;
    __shared__ float feat[FEAT];
    __shared__ float h[Cn];
    __shared__ float lg[En];

    // fold pooled partials for channel `tid` (fixed order -> deterministic)
    {
        const float* pp = g_part + (b * Cn + tid) * NPB2;
        float sum = 0.f;
#pragma unroll 8
        for (int k = 0; k < NPB2; k++) sum += pp[k];
        feat[tid] = sum * (1.f / (float)HWn) + pwb[tid];
    }
    for (int k = tid; k < TDn; k += 128) feat[Cn + k] = t_emb[b * TDn + k];
    for (int k = tid; k < CDn; k += 128) feat[Cn + TDn + k] = c_emb[b * CDn + k];
    __syncthreads();

    float s = b1[tid];
    for (int k = 0; k < FEAT; k++) s += feat[k] * w1[k * Cn + tid];
    h[tid] = silu_f(s);
    __syncthreads();

    if (tid < En) {
        float acc = b2[tid];
        for (int j = 0; j < Cn; j++) acc += h[j] * w2[j * En + tid];
        lg[tid] = acc;
        logits_out[b * En + tid] = acc;
    }
    __syncthreads();

    if (tid == 0) {
        int i0 = 0;
        float v0 = lg[0];
#pragma unroll
        for (int e = 1; e < En; e++)
            if (lg[e] > v0) { v0 = lg[e]; i0 = e; }
        int i1 = -1;
        float v1 = -3.4e38f;
#pragma unroll
        for (int e = 0; e < En; e++)
            if (e != i0 && lg[e] > v1) { v1 = lg[e]; i1 = e; }
        float e1x = __expf(v1 - v0);
        float inv = 1.f / (1.f + e1x);
        g_idx[b * 2 + 0] = i0;
        g_idx[b * 2 + 1] = i1;
        g_wts[b * 2 + 0] = inv;
        g_wts[b * 2 + 1] = e1x * inv;
    }
}

// ---------------- launcher ----------------------------------------------------
extern "C" void kernel_launch(void* const* d_in, const int* in_sizes, int n_in,
                              void* d_out, int out_size) {
    const float* x        = (const float*)d_in[0];
    const float* t_emb    = (const float*)d_in[1];
    const float* c_emb    = (const float*)d_in[2];
    const float* proj_dw  = (const float*)d_in[3];
    const float* proj_dwb = (const float*)d_in[4];
    const float* proj_pw  = (const float*)d_in[5];
    const float* proj_pwb = (const float*)d_in[6];
    const float* rw1      = (const float*)d_in[7];
    const float* rb1      = (const float*)d_in[8];
    const float* rw2      = (const float*)d_in[9];
    const float* rb2      = (const float*)d_in[10];
    const float* exp_dw   = (const float*)d_in[11];
    const float* exp_dwb  = (const float*)d_in[12];
    const float* exp_pw   = (const float*)d_in[13];
    const float* exp_pwb  = (const float*)d_in[14];
    float* out = (float*)d_out;

    // 1) proj depthwise
    dw_proj_kernel<<<dim3(Cn, Bn), 256>>>(x, proj_dw, proj_dwb);
    // 2) proj pointwise GEMM (tf32 tensor cores) + fused pooled partials
    pw_proj_gemm<<<dim3(NPB, 1, Bn), 256>>>(proj_pw, proj_pwb);
    // 3) router (folds partials, writes logits into tail of d_out)
    router_kernel<<<Bn, 128>>>(t_emb, c_emb, proj_pwb, rw1, rb1, rw2, rb2,
                               out + Bn * Cn * HWn);
    // 4) expert depthwise: both routed slots from one staged tile
    dw_expert_both<<<dim3(Cn, Bn), 256>>>(exp_dw, exp_dwb);
    // 5) expert pointwise GEMM (tf32) + silu + weighted combine -> out
    pw_expert_gemm<<<dim3(NPB, 1, Bn), 256>>>(exp_pw, exp_pwb, out);
}